// round 7
// baseline (speedup 1.0000x reference)
#include <cuda_runtime.h>
#include <math.h>
#include <stdint.h>

#define NNODE 50000
#define NEDGE 800000
#define FIN   128
#define FOUT  64
#define NEG_SLOPE 0.2f
#define NB_SCAN 49            // ceil(NNODE/1024)

// ---------------- scratch (device globals: no allocation allowed) -------------
__device__ float g_xl[NNODE * FOUT];
__device__ float g_xr[NNODE * FOUT];
__device__ int   g_deg[NNODE];
__device__ int   g_off[NNODE];
__device__ int   g_cursor[NNODE];
__device__ int   g_csr[NEDGE];
__device__ int   g_is64;

// ---------------- init: zero degree + detect edge_index dtype ----------------
__global__ void init_kernel(const void* __restrict__ ei) {
    int i = blockIdx.x * blockDim.x + threadIdx.x;
    for (int k = i; k < NNODE; k += gridDim.x * blockDim.x) g_deg[k] = 0;
    if (blockIdx.x == 0 && threadIdx.x < 32) {
        const long long* p = (const long long*)ei;
        int lane = threadIdx.x;
        int ok = 1;
#pragma unroll
        for (int j = 0; j < 8; ++j) {
            long long v = p[lane * 8 + j];
            if (v < 0 || v >= (long long)NNODE) ok = 0;
        }
        unsigned all = __ballot_sync(0xffffffffu, ok);
        if (lane == 0) g_is64 = (all == 0xffffffffu) ? 1 : 0;
    }
}

// ---------------- 3xTF32 tensor-core GEMM (48KB static smem) ------------------
// Per block: 256 thr (8 warps), 32 X-rows, two passes (Wl half, Wr half).
// Warp w: m-tile = (w>>2)*16 rows, n-tile = (w&3)*16 cols (2 n8 frags).
// Smem float4 cells with XOR swizzle: cell(r,c4) -> r*32 + (c4 ^ (r&7)).
// 3xTF32: v = hi + lo; lo passed raw (residual fits tf32 precision budget).

__device__ __forceinline__ void tf32_split(float v, uint32_t& hi, uint32_t& lo) {
    asm("cvt.rna.tf32.f32 %0, %1;" : "=r"(hi) : "f"(v));
    lo = __float_as_uint(v - __uint_as_float(hi));
}

__device__ __forceinline__ void mma_tf32(float c[4], const uint32_t a[4],
                                         uint32_t b0, uint32_t b1) {
    asm volatile(
        "mma.sync.aligned.m16n8k8.row.col.f32.tf32.tf32.f32 "
        "{%0,%1,%2,%3}, {%4,%5,%6,%7}, {%8,%9}, {%0,%1,%2,%3};"
        : "+f"(c[0]), "+f"(c[1]), "+f"(c[2]), "+f"(c[3])
        : "r"(a[0]), "r"(a[1]), "r"(a[2]), "r"(a[3]), "r"(b0), "r"(b1));
}

__global__ void __launch_bounds__(256) gemm_kernel(
        const float* __restrict__ x,
        const float* __restrict__ Wl,
        const float* __restrict__ bl,
        const float* __restrict__ Wr,
        const float* __restrict__ br) {
    __shared__ float4 sX4[32 * 32];   // 16 KB
    __shared__ float4 sW4[64 * 32];   // 32 KB

    const int tid = threadIdx.x;
    const int rowBase = blockIdx.x * 32;

    const float4* x4 = (const float4*)x;
    for (int i = tid; i < 32 * 32; i += 256) {
        int r = i >> 5, c = i & 31;
        int row = rowBase + r;
        sX4[r * 32 + (c ^ (r & 7))] =
            (row < NNODE) ? x4[row * 32 + c] : make_float4(0.f, 0.f, 0.f, 0.f);
    }

    const int w    = tid >> 5;
    const int lane = tid & 31;
    const int g    = lane >> 2;
    const int tig  = lane & 3;
    const int mw   = (w >> 2) * 16;
    const int nw   = (w & 3) * 16;

#pragma unroll
    for (int p = 0; p < 2; ++p) {
        const float4* w4 = p ? (const float4*)Wr : (const float4*)Wl;
        __syncthreads();
        for (int i = tid; i < 64 * 32; i += 256) {
            int r = i >> 5, c = i & 31;
            sW4[r * 32 + (c ^ (r & 7))] = w4[r * 32 + c];
        }
        __syncthreads();

        float acc[2][4];
#pragma unroll
        for (int j = 0; j < 2; ++j)
#pragma unroll
            for (int q = 0; q < 4; ++q) acc[j][q] = 0.f;

        const int r0 = mw + g, r1 = mw + 8 + g;

#pragma unroll
        for (int ks = 0; ks < 16; ++ks) {
            const int c4a = 2 * ks;
            const int c4b = 2 * ks + 1;
            float af[4];
            af[0] = ((const float*)&sX4[r0 * 32 + (c4a ^ (r0 & 7))])[tig];
            af[1] = ((const float*)&sX4[r1 * 32 + (c4a ^ (r1 & 7))])[tig];
            af[2] = ((const float*)&sX4[r0 * 32 + (c4b ^ (r0 & 7))])[tig];
            af[3] = ((const float*)&sX4[r1 * 32 + (c4b ^ (r1 & 7))])[tig];
            uint32_t ahi[4], alo[4];
#pragma unroll
            for (int q = 0; q < 4; ++q) tf32_split(af[q], ahi[q], alo[q]);

#pragma unroll
            for (int j = 0; j < 2; ++j) {
                const int br_ = nw + j * 8 + g;
                float b0f = ((const float*)&sW4[br_ * 32 + (c4a ^ (br_ & 7))])[tig];
                float b1f = ((const float*)&sW4[br_ * 32 + (c4b ^ (br_ & 7))])[tig];
                uint32_t b0h, b0l, b1h, b1l;
                tf32_split(b0f, b0h, b0l);
                tf32_split(b1f, b1h, b1l);
                mma_tf32(acc[j], ahi, b0h, b1h);   // hi*hi
                mma_tf32(acc[j], ahi, b0l, b1l);   // hi*lo
                mma_tf32(acc[j], alo, b0h, b1h);   // lo*hi
            }
        }

        float* dstbuf = p ? g_xr : g_xl;
        const float* bb = p ? br : bl;
#pragma unroll
        for (int j = 0; j < 2; ++j) {
            int cc = nw + j * 8 + 2 * tig;
            float bias0 = bb[cc], bias1 = bb[cc + 1];
            int row0 = rowBase + mw + g;
            if (row0 < NNODE) {
                float2 o = make_float2(acc[j][0] + bias0, acc[j][1] + bias1);
                *(float2*)(dstbuf + row0 * 64 + cc) = o;
            }
            int row1 = row0 + 8;
            if (row1 < NNODE) {
                float2 o = make_float2(acc[j][2] + bias0, acc[j][3] + bias1);
                *(float2*)(dstbuf + row1 * 64 + cc) = o;
            }
        }
    }
}

// ---------------- degree histogram -------------------------------------------
__global__ void deg_kernel(const void* __restrict__ ei) {
    const int stride = gridDim.x * blockDim.x;
    const int is64 = g_is64;
    for (int i = blockIdx.x * blockDim.x + threadIdx.x; i < NEDGE; i += stride) {
        int d;
        if (is64) d = (int)((const long long*)ei)[NEDGE + i];
        else      d = ((const int*)ei)[NEDGE + i];
        atomicAdd(&g_deg[d], 1);
    }
}

// ---------------- single-block full scan: g_off (+seed g_cursor) --------------
__global__ void scan_all_kernel() {
    __shared__ int ws[32];
    __shared__ int carry;
    const int tid = threadIdx.x;
    const int lane = tid & 31, wid = tid >> 5;
    if (tid == 0) carry = 0;
    __syncthreads();

    for (int chunk = 0; chunk < NB_SCAN; ++chunk) {
        int i = chunk * 1024 + tid;
        int v = (i < NNODE) ? g_deg[i] : 0;
        int xx = v;
#pragma unroll
        for (int o = 1; o < 32; o <<= 1) {
            int y = __shfl_up_sync(0xffffffffu, xx, o);
            if (lane >= o) xx += y;
        }
        if (lane == 31) ws[wid] = xx;
        __syncthreads();
        if (wid == 0) {
            int y = ws[lane];
#pragma unroll
            for (int o = 1; o < 32; o <<= 1) {
                int z = __shfl_up_sync(0xffffffffu, y, o);
                if (lane >= o) y += z;
            }
            ws[lane] = y;
        }
        __syncthreads();
        int incl = xx + (wid ? ws[wid - 1] : 0);
        int excl = carry + incl - v;
        if (i < NNODE) {
            g_off[i]    = excl;
            g_cursor[i] = excl;   // scatter atomics start at the row offset
        }
        __syncthreads();          // everyone has read carry & ws
        if (tid == 1023) carry += incl;
        __syncthreads();
    }
}

// ---------------- scatter edges into CSR (cursor holds absolute pos) ----------
__global__ void scatter_kernel(const void* __restrict__ ei) {
    const int stride = gridDim.x * blockDim.x;
    const int is64 = g_is64;
    for (int i = blockIdx.x * blockDim.x + threadIdx.x; i < NEDGE; i += stride) {
        int s, d;
        if (is64) {
            s = (int)((const long long*)ei)[i];
            d = (int)((const long long*)ei)[NEDGE + i];
        } else {
            s = ((const int*)ei)[i];
            d = ((const int*)ei)[NEDGE + i];
        }
        int pos = atomicAdd(&g_cursor[d], 1);
        g_csr[pos] = s;
    }
}

// ---------------- aggregation: warp/dst, online softmax, 4-edge ILP -----------
__global__ void aggregate_kernel(const float* __restrict__ att,
                                 const float* __restrict__ bias,
                                 float* __restrict__ out) {
    int gw   = (blockIdx.x * blockDim.x + threadIdx.x) >> 5;
    int lane = threadIdx.x & 31;
    if (gw >= NNODE) return;
    const int dst = gw;

    const float2* xl2 = (const float2*)g_xl;
    const float2 a    = ((const float2*)att)[lane];
    const float2 xr   = ((const float2*)g_xr)[dst * 32 + lane];

    const int start   = g_off[dst];
    const int n_items = g_deg[dst] + 1;    // item 0 = self-loop

    float m = -INFINITY, s = 0.f;
    float2 acc = make_float2(0.f, 0.f);

    for (int t = 0; t < n_items; t += 4) {
        const int nb = min(4, n_items - t);
        float2 v[4];
        float  p[4];
        // issue all gathers first (independent), then the dots
#pragma unroll
        for (int q = 0; q < 4; ++q) {
            if (q < nb) {
                int item = t + q;
                int sn = (item == 0) ? dst : g_csr[start + item - 1];
                v[q] = xl2[sn * 32 + lane];
            }
        }
#pragma unroll
        for (int q = 0; q < 4; ++q) {
            if (q < nb) {
                float h0 = v[q].x + xr.x; h0 = h0 > 0.f ? h0 : NEG_SLOPE * h0;
                float h1 = v[q].y + xr.y; h1 = h1 > 0.f ? h1 : NEG_SLOPE * h1;
                p[q] = a.x * h0 + a.y * h1;
            } else {
                p[q] = 0.f;   // reduced but unused
            }
        }
        // 4 interleaved butterfly reductions (independent latency chains)
#pragma unroll
        for (int o = 16; o; o >>= 1) {
#pragma unroll
            for (int q = 0; q < 4; ++q)
                p[q] += __shfl_xor_sync(0xffffffffu, p[q], o);
        }
        // sequential online-softmax updates (cheap ALU chain)
#pragma unroll
        for (int q = 0; q < 4; ++q) {
            if (q < nb) {
                float mn = fmaxf(m, p[q]);
                float cs = __expf(m - mn);     // 0 on first item (m = -inf)
                float ce = __expf(p[q] - mn);
                s     = s * cs + ce;
                acc.x = acc.x * cs + ce * v[q].x;
                acc.y = acc.y * cs + ce * v[q].y;
                m = mn;
            }
        }
    }

    float inv = 1.f / s;
    float2 bv = ((const float2*)bias)[lane];
    float2 o = make_float2(fmaxf(acc.x * inv + bv.x, 0.f),
                           fmaxf(acc.y * inv + bv.y, 0.f));
    ((float2*)out)[dst * 32 + lane] = o;
}

// ---------------- launch: fork GEMM || CSR build, join before aggregate -------
extern "C" void kernel_launch(void* const* d_in, const int* in_sizes, int n_in,
                              void* d_out, int out_size) {
    const float* x    = (const float*)d_in[0];
    const float* Wl   = (const float*)d_in[1];
    const float* bl   = (const float*)d_in[2];
    const float* Wr   = (const float*)d_in[3];
    const float* br   = (const float*)d_in[4];
    const float* att  = (const float*)d_in[5];
    const float* bias = (const float*)d_in[6];
    const void*  ei   = (const void*)d_in[7];
    float* out = (float*)d_out;

    cudaStream_t s2;
    cudaEvent_t evFork, evJoin;
    cudaStreamCreateWithFlags(&s2, cudaStreamNonBlocking);
    cudaEventCreateWithFlags(&evFork, cudaEventDisableTiming);
    cudaEventCreateWithFlags(&evJoin, cudaEventDisableTiming);

    init_kernel<<<NB_SCAN, 1024>>>(ei);
    cudaEventRecord(evFork, 0);

    // Side stream: CSR build.
    cudaStreamWaitEvent(s2, evFork, 0);
    deg_kernel<<<1184, 256, 0, s2>>>(ei);
    scan_all_kernel<<<1, 1024, 0, s2>>>();
    scatter_kernel<<<1184, 256, 0, s2>>>(ei);
    cudaEventRecord(evJoin, s2);

    // Main stream: GEMM concurrently.
    gemm_kernel<<<(NNODE + 31) / 32, 256>>>(x, Wl, bl, Wr, br);

    cudaStreamWaitEvent(0, evJoin, 0);
    aggregate_kernel<<<(NNODE * 32 + 255) / 256, 256>>>(att, bias, out);

    cudaEventDestroy(evFork);
    cudaEventDestroy(evJoin);
    cudaStreamDestroy(s2);
}

// round 8
// speedup vs baseline: 1.1996x; 1.1996x over previous
#include <cuda_runtime.h>
#include <math.h>
#include <stdint.h>

#define NNODE 50000
#define NEDGE 800000
#define FIN   128
#define FOUT  64
#define NEG_SLOPE 0.2f
#define NB_SCAN 49            // ceil(NNODE/1024)

// ---------------- scratch (device globals: no allocation allowed) -------------
__device__ float g_xl[NNODE * FOUT];
__device__ float g_xr[NNODE * FOUT];
__device__ int   g_deg[NNODE];
__device__ int   g_off[NNODE];
__device__ int   g_cursor[NNODE];
__device__ int   g_csr[NEDGE];
__device__ int   g_bsum[NB_SCAN];
__device__ int   g_is64;

// ---------------- init: zero degree + detect edge_index dtype ----------------
__global__ void init_kernel(const void* __restrict__ ei) {
    int i = blockIdx.x * blockDim.x + threadIdx.x;
    for (int k = i; k < NNODE; k += gridDim.x * blockDim.x) g_deg[k] = 0;
    if (blockIdx.x == 0 && threadIdx.x < 32) {
        const long long* p = (const long long*)ei;
        int lane = threadIdx.x;
        int ok = 1;
#pragma unroll
        for (int j = 0; j < 8; ++j) {
            long long v = p[lane * 8 + j];
            if (v < 0 || v >= (long long)NNODE) ok = 0;
        }
        unsigned all = __ballot_sync(0xffffffffu, ok);
        if (lane == 0) g_is64 = (all == 0xffffffffu) ? 1 : 0;
    }
}

// ---------------- 3xTF32 tensor-core GEMM (48KB static smem) ------------------
__device__ __forceinline__ void tf32_split(float v, uint32_t& hi, uint32_t& lo) {
    asm("cvt.rna.tf32.f32 %0, %1;" : "=r"(hi) : "f"(v));
    lo = __float_as_uint(v - __uint_as_float(hi));
}

__device__ __forceinline__ void mma_tf32(float c[4], const uint32_t a[4],
                                         uint32_t b0, uint32_t b1) {
    asm volatile(
        "mma.sync.aligned.m16n8k8.row.col.f32.tf32.tf32.f32 "
        "{%0,%1,%2,%3}, {%4,%5,%6,%7}, {%8,%9}, {%0,%1,%2,%3};"
        : "+f"(c[0]), "+f"(c[1]), "+f"(c[2]), "+f"(c[3])
        : "r"(a[0]), "r"(a[1]), "r"(a[2]), "r"(a[3]), "r"(b0), "r"(b1));
}

__global__ void __launch_bounds__(256) gemm_kernel(
        const float* __restrict__ x,
        const float* __restrict__ Wl,
        const float* __restrict__ bl,
        const float* __restrict__ Wr,
        const float* __restrict__ br) {
    __shared__ float4 sX4[32 * 32];   // 16 KB
    __shared__ float4 sW4[64 * 32];   // 32 KB

    const int tid = threadIdx.x;
    const int rowBase = blockIdx.x * 32;

    const float4* x4 = (const float4*)x;
    for (int i = tid; i < 32 * 32; i += 256) {
        int r = i >> 5, c = i & 31;
        int row = rowBase + r;
        sX4[r * 32 + (c ^ (r & 7))] =
            (row < NNODE) ? x4[row * 32 + c] : make_float4(0.f, 0.f, 0.f, 0.f);
    }

    const int w    = tid >> 5;
    const int lane = tid & 31;
    const int g    = lane >> 2;
    const int tig  = lane & 3;
    const int mw   = (w >> 2) * 16;
    const int nw   = (w & 3) * 16;

#pragma unroll
    for (int p = 0; p < 2; ++p) {
        const float4* w4 = p ? (const float4*)Wr : (const float4*)Wl;
        __syncthreads();
        for (int i = tid; i < 64 * 32; i += 256) {
            int r = i >> 5, c = i & 31;
            sW4[r * 32 + (c ^ (r & 7))] = w4[r * 32 + c];
        }
        __syncthreads();

        float acc[2][4];
#pragma unroll
        for (int j = 0; j < 2; ++j)
#pragma unroll
            for (int q = 0; q < 4; ++q) acc[j][q] = 0.f;

        const int r0 = mw + g, r1 = mw + 8 + g;

#pragma unroll
        for (int ks = 0; ks < 16; ++ks) {
            const int c4a = 2 * ks;
            const int c4b = 2 * ks + 1;
            float af[4];
            af[0] = ((const float*)&sX4[r0 * 32 + (c4a ^ (r0 & 7))])[tig];
            af[1] = ((const float*)&sX4[r1 * 32 + (c4a ^ (r1 & 7))])[tig];
            af[2] = ((const float*)&sX4[r0 * 32 + (c4b ^ (r0 & 7))])[tig];
            af[3] = ((const float*)&sX4[r1 * 32 + (c4b ^ (r1 & 7))])[tig];
            uint32_t ahi[4], alo[4];
#pragma unroll
            for (int q = 0; q < 4; ++q) tf32_split(af[q], ahi[q], alo[q]);

#pragma unroll
            for (int j = 0; j < 2; ++j) {
                const int br_ = nw + j * 8 + g;
                float b0f = ((const float*)&sW4[br_ * 32 + (c4a ^ (br_ & 7))])[tig];
                float b1f = ((const float*)&sW4[br_ * 32 + (c4b ^ (br_ & 7))])[tig];
                uint32_t b0h, b0l, b1h, b1l;
                tf32_split(b0f, b0h, b0l);
                tf32_split(b1f, b1h, b1l);
                mma_tf32(acc[j], ahi, b0h, b1h);   // hi*hi
                mma_tf32(acc[j], ahi, b0l, b1l);   // hi*lo
                mma_tf32(acc[j], alo, b0h, b1h);   // lo*hi
            }
        }

        float* dstbuf = p ? g_xr : g_xl;
        const float* bb = p ? br : bl;
#pragma unroll
        for (int j = 0; j < 2; ++j) {
            int cc = nw + j * 8 + 2 * tig;
            float bias0 = bb[cc], bias1 = bb[cc + 1];
            int row0 = rowBase + mw + g;
            if (row0 < NNODE) {
                float2 o = make_float2(acc[j][0] + bias0, acc[j][1] + bias1);
                *(float2*)(dstbuf + row0 * 64 + cc) = o;
            }
            int row1 = row0 + 8;
            if (row1 < NNODE) {
                float2 o = make_float2(acc[j][2] + bias0, acc[j][3] + bias1);
                *(float2*)(dstbuf + (row1) * 64 + cc) = o;
            }
        }
    }
}

// ---------------- degree histogram (4-wide batched atomics) -------------------
#define EDGE_GRID 782          // 782*256*4 >= NEDGE
__global__ void deg_kernel(const void* __restrict__ ei) {
    const int stride = EDGE_GRID * 256;
    const int i0 = blockIdx.x * 256 + threadIdx.x;
    const int is64 = g_is64;
    int d[4];
#pragma unroll
    for (int q = 0; q < 4; ++q) {
        int i = i0 + q * stride;
        d[q] = -1;
        if (i < NEDGE)
            d[q] = is64 ? (int)((const long long*)ei)[NEDGE + i]
                        : ((const int*)ei)[NEDGE + i];
    }
#pragma unroll
    for (int q = 0; q < 4; ++q)
        if (d[q] >= 0) atomicAdd(&g_deg[d[q]], 1);
}

// ---------------- per-block scan of degrees ----------------------------------
__global__ void scan_kernel() {
    int i = blockIdx.x * 1024 + threadIdx.x;
    int v = (i < NNODE) ? g_deg[i] : 0;
    int xx = v;
    int lane = threadIdx.x & 31, wid = threadIdx.x >> 5;
#pragma unroll
    for (int o = 1; o < 32; o <<= 1) {
        int y = __shfl_up_sync(0xffffffffu, xx, o);
        if (lane >= o) xx += y;
    }
    __shared__ int ws[32];
    if (lane == 31) ws[wid] = xx;
    __syncthreads();
    if (wid == 0) {
        int y = ws[lane];
#pragma unroll
        for (int o = 1; o < 32; o <<= 1) {
            int z = __shfl_up_sync(0xffffffffu, y, o);
            if (lane >= o) y += z;
        }
        ws[lane] = y;
    }
    __syncthreads();
    int incl = xx + (wid ? ws[wid - 1] : 0);
    if (i < NNODE) g_off[i] = incl - v;                  // block-local exclusive
    if (threadIdx.x == 1023) g_bsum[blockIdx.x] = incl;  // block total
}

// ---------------- fixup: parallel bsum load + add; also seeds cursor ----------
__global__ void fixup_kernel() {
    __shared__ int sb[NB_SCAN];
    __shared__ int pref;
    if (threadIdx.x < NB_SCAN) sb[threadIdx.x] = g_bsum[threadIdx.x];
    __syncthreads();
    if (threadIdx.x == 0) {
        int run = 0;
        for (int b = 0; b < blockIdx.x; ++b) run += sb[b];
        pref = run;
    }
    __syncthreads();
    int i = blockIdx.x * 1024 + threadIdx.x;
    if (i < NNODE) {
        int o = g_off[i] + pref;
        g_off[i]    = o;
        g_cursor[i] = o;          // scatter atomics start at the row offset
    }
}

// ---------------- scatter (4-wide batched: 4 atomics in flight) ---------------
__global__ void scatter_kernel(const void* __restrict__ ei) {
    const int stride = EDGE_GRID * 256;
    const int i0 = blockIdx.x * 256 + threadIdx.x;
    const int is64 = g_is64;
    int s[4], d[4], pos[4];
#pragma unroll
    for (int q = 0; q < 4; ++q) {
        int i = i0 + q * stride;
        d[q] = -1;
        if (i < NEDGE) {
            if (is64) {
                s[q] = (int)((const long long*)ei)[i];
                d[q] = (int)((const long long*)ei)[NEDGE + i];
            } else {
                s[q] = ((const int*)ei)[i];
                d[q] = ((const int*)ei)[NEDGE + i];
            }
        }
    }
#pragma unroll
    for (int q = 0; q < 4; ++q)
        if (d[q] >= 0) pos[q] = atomicAdd(&g_cursor[d[q]], 1);
#pragma unroll
    for (int q = 0; q < 4; ++q)
        if (d[q] >= 0) g_csr[pos[q]] = s[q];
}

// ---------------- aggregation: warp/dst, online softmax, 4-edge ILP -----------
__global__ void aggregate_kernel(const float* __restrict__ att,
                                 const float* __restrict__ bias,
                                 float* __restrict__ out) {
    int gw   = (blockIdx.x * blockDim.x + threadIdx.x) >> 5;
    int lane = threadIdx.x & 31;
    if (gw >= NNODE) return;
    const int dst = gw;

    const float2* xl2 = (const float2*)g_xl;
    const float2 a    = ((const float2*)att)[lane];
    const float2 xr   = ((const float2*)g_xr)[dst * 32 + lane];

    const int start   = g_off[dst];
    const int n_items = g_deg[dst] + 1;    // item 0 = self-loop

    float m = -INFINITY, s = 0.f;
    float2 acc = make_float2(0.f, 0.f);

    for (int t = 0; t < n_items; t += 4) {
        const int nb = min(4, n_items - t);
        float2 v[4];
        float  p[4];
#pragma unroll
        for (int q = 0; q < 4; ++q) {
            if (q < nb) {
                int item = t + q;
                int sn = (item == 0) ? dst : g_csr[start + item - 1];
                v[q] = xl2[sn * 32 + lane];
            }
        }
#pragma unroll
        for (int q = 0; q < 4; ++q) {
            if (q < nb) {
                float h0 = v[q].x + xr.x; h0 = h0 > 0.f ? h0 : NEG_SLOPE * h0;
                float h1 = v[q].y + xr.y; h1 = h1 > 0.f ? h1 : NEG_SLOPE * h1;
                p[q] = a.x * h0 + a.y * h1;
            } else {
                p[q] = 0.f;
            }
        }
#pragma unroll
        for (int o = 16; o; o >>= 1) {
#pragma unroll
            for (int q = 0; q < 4; ++q)
                p[q] += __shfl_xor_sync(0xffffffffu, p[q], o);
        }
#pragma unroll
        for (int q = 0; q < 4; ++q) {
            if (q < nb) {
                float mn = fmaxf(m, p[q]);
                float cs = __expf(m - mn);
                float ce = __expf(p[q] - mn);
                s     = s * cs + ce;
                acc.x = acc.x * cs + ce * v[q].x;
                acc.y = acc.y * cs + ce * v[q].y;
                m = mn;
            }
        }
    }

    float inv = 1.f / s;
    float2 bv = ((const float2*)bias)[lane];
    float2 o = make_float2(fmaxf(acc.x * inv + bv.x, 0.f),
                           fmaxf(acc.y * inv + bv.y, 0.f));
    ((float2*)out)[dst * 32 + lane] = o;
}

// ---------------- launch: fork GEMM || CSR build, join before aggregate -------
extern "C" void kernel_launch(void* const* d_in, const int* in_sizes, int n_in,
                              void* d_out, int out_size) {
    const float* x    = (const float*)d_in[0];
    const float* Wl   = (const float*)d_in[1];
    const float* bl   = (const float*)d_in[2];
    const float* Wr   = (const float*)d_in[3];
    const float* br   = (const float*)d_in[4];
    const float* att  = (const float*)d_in[5];
    const float* bias = (const float*)d_in[6];
    const void*  ei   = (const void*)d_in[7];
    float* out = (float*)d_out;

    cudaStream_t s2;
    cudaEvent_t evFork, evJoin;
    cudaStreamCreateWithFlags(&s2, cudaStreamNonBlocking);
    cudaEventCreateWithFlags(&evFork, cudaEventDisableTiming);
    cudaEventCreateWithFlags(&evJoin, cudaEventDisableTiming);

    init_kernel<<<NB_SCAN, 1024>>>(ei);
    cudaEventRecord(evFork, 0);

    // Side stream: CSR build.
    cudaStreamWaitEvent(s2, evFork, 0);
    deg_kernel<<<EDGE_GRID, 256, 0, s2>>>(ei);
    scan_kernel<<<NB_SCAN, 1024, 0, s2>>>();
    fixup_kernel<<<NB_SCAN, 1024, 0, s2>>>();
    scatter_kernel<<<EDGE_GRID, 256, 0, s2>>>(ei);
    cudaEventRecord(evJoin, s2);

    // Main stream: GEMM concurrently.
    gemm_kernel<<<(NNODE + 31) / 32, 256>>>(x, Wl, bl, Wr, br);

    cudaStreamWaitEvent(0, evJoin, 0);
    aggregate_kernel<<<(NNODE * 32 + 255) / 256, 256>>>(att, bias, out);

    cudaEventDestroy(evFork);
    cudaEventDestroy(evJoin);
    cudaStreamDestroy(s2);
}

// round 9
// speedup vs baseline: 1.3410x; 1.1178x over previous
#include <cuda_runtime.h>
#include <math.h>
#include <stdint.h>

#define NNODE 50000
#define NEDGE 800000
#define FIN   128
#define FOUT  64
#define NEG_SLOPE 0.2f
#define NB_SCAN 49            // ceil(NNODE/1024)

// ---------------- scratch (device globals: no allocation allowed) -------------
__device__ float g_xl[NNODE * FOUT];
__device__ float g_xr[NNODE * FOUT];
__device__ int   g_deg[NNODE];
__device__ int   g_off[NNODE];
__device__ int   g_cursor[NNODE];
__device__ int   g_csr[NEDGE];
__device__ int   g_bsum[NB_SCAN];
__device__ int   g_is64;

// ---------------- init: zero degree + detect edge_index dtype ----------------
__global__ void init_kernel(const void* __restrict__ ei) {
    int i = blockIdx.x * blockDim.x + threadIdx.x;
    for (int k = i; k < NNODE; k += gridDim.x * blockDim.x) g_deg[k] = 0;
    if (blockIdx.x == 0 && threadIdx.x < 32) {
        const long long* p = (const long long*)ei;
        int lane = threadIdx.x;
        int ok = 1;
#pragma unroll
        for (int j = 0; j < 8; ++j) {
            long long v = p[lane * 8 + j];
            if (v < 0 || v >= (long long)NNODE) ok = 0;
        }
        unsigned all = __ballot_sync(0xffffffffu, ok);
        if (lane == 0) g_is64 = (all == 0xffffffffu) ? 1 : 0;
    }
}

// ---------------- 3xBF16 tensor-core GEMM (48KB static smem) ------------------
// Same tiling as the 3xTF32 version but mma.m16n8k16.bf16: k=16 per MMA,
// halving MMA count. Error compensation: v = hi + lo (both bf16);
// acc += hi*hi + hi*lo + lo*hi (fp32 accum). Residual ~2^-18 per product.
// Fragment packing: bf16x2 reg = {low half: element k (even), high: k+1}.

__device__ __forceinline__ void bf16_split(float e, float o,
                                           uint32_t& hi, uint32_t& lo) {
    // hi = pack(bf16(e) low, bf16(o) high)
    asm("cvt.rn.bf16x2.f32 %0, %1, %2;" : "=r"(hi) : "f"(o), "f"(e));
    float eh = __uint_as_float(hi << 16);
    float oh = __uint_as_float(hi & 0xffff0000u);
    float er = e - eh;
    float orr = o - oh;
    asm("cvt.rn.bf16x2.f32 %0, %1, %2;" : "=r"(lo) : "f"(orr), "f"(er));
}

__device__ __forceinline__ void mma_bf16(float c[4], const uint32_t a[4],
                                         uint32_t b0, uint32_t b1) {
    asm volatile(
        "mma.sync.aligned.m16n8k16.row.col.f32.bf16.bf16.f32 "
        "{%0,%1,%2,%3}, {%4,%5,%6,%7}, {%8,%9}, {%0,%1,%2,%3};"
        : "+f"(c[0]), "+f"(c[1]), "+f"(c[2]), "+f"(c[3])
        : "r"(a[0]), "r"(a[1]), "r"(a[2]), "r"(a[3]), "r"(b0), "r"(b1));
}

// load float2 at (row r, float-col c) from XOR-swizzled float4 array (32 cells/row)
__device__ __forceinline__ float2 lds2_sw(const float4* s4, int r, int c) {
    const float* p = (const float*)&s4[r * 32 + (((c >> 2)) ^ (r & 7)) ] + (c & 3);
    return *(const float2*)p;
}

__global__ void __launch_bounds__(256) gemm_kernel(
        const float* __restrict__ x,
        const float* __restrict__ Wl,
        const float* __restrict__ bl,
        const float* __restrict__ Wr,
        const float* __restrict__ br) {
    __shared__ float4 sX4[32 * 32];   // 16 KB: 32 rows x 128 k
    __shared__ float4 sW4[64 * 32];   // 32 KB: 64 cols x 128 k (one W half)

    const int tid = threadIdx.x;
    const int rowBase = blockIdx.x * 32;

    const float4* x4 = (const float4*)x;
    for (int i = tid; i < 32 * 32; i += 256) {
        int r = i >> 5, c = i & 31;
        int row = rowBase + r;
        sX4[r * 32 + (c ^ (r & 7))] =
            (row < NNODE) ? x4[row * 32 + c] : make_float4(0.f, 0.f, 0.f, 0.f);
    }

    const int w    = tid >> 5;
    const int lane = tid & 31;
    const int g    = lane >> 2;    // 0..7
    const int tig  = lane & 3;     // 0..3
    const int mw   = (w >> 2) * 16;
    const int nw   = (w & 3) * 16;

#pragma unroll
    for (int p = 0; p < 2; ++p) {
        const float4* w4 = p ? (const float4*)Wr : (const float4*)Wl;
        __syncthreads();
        for (int i = tid; i < 64 * 32; i += 256) {
            int r = i >> 5, c = i & 31;
            sW4[r * 32 + (c ^ (r & 7))] = w4[r * 32 + c];
        }
        __syncthreads();

        float acc[2][4];
#pragma unroll
        for (int j = 0; j < 2; ++j)
#pragma unroll
            for (int q = 0; q < 4; ++q) acc[j][q] = 0.f;

        const int r0 = mw + g, r1 = mw + 8 + g;

#pragma unroll
        for (int ks = 0; ks < 8; ++ks) {
            const int k0 = ks * 16;
            // A fragment: a0=(g,k0+2tig..+1) a1=(g+8,..) a2=(g,k0+8+2tig..) a3=(g+8,..)
            float2 fa0 = lds2_sw(sX4, r0, k0 + 2 * tig);
            float2 fa1 = lds2_sw(sX4, r1, k0 + 2 * tig);
            float2 fa2 = lds2_sw(sX4, r0, k0 + 8 + 2 * tig);
            float2 fa3 = lds2_sw(sX4, r1, k0 + 8 + 2 * tig);
            uint32_t ahi[4], alo[4];
            bf16_split(fa0.x, fa0.y, ahi[0], alo[0]);
            bf16_split(fa1.x, fa1.y, ahi[1], alo[1]);
            bf16_split(fa2.x, fa2.y, ahi[2], alo[2]);
            bf16_split(fa3.x, fa3.y, ahi[3], alo[3]);

#pragma unroll
            for (int j = 0; j < 2; ++j) {
                const int br_ = nw + j * 8 + g;   // W row (= output col)
                float2 fb0 = lds2_sw(sW4, br_, k0 + 2 * tig);
                float2 fb1 = lds2_sw(sW4, br_, k0 + 8 + 2 * tig);
                uint32_t b0h, b0l, b1h, b1l;
                bf16_split(fb0.x, fb0.y, b0h, b0l);
                bf16_split(fb1.x, fb1.y, b1h, b1l);
                mma_bf16(acc[j], ahi, b0h, b1h);   // hi*hi
                mma_bf16(acc[j], ahi, b0l, b1l);   // hi*lo
                mma_bf16(acc[j], alo, b0h, b1h);   // lo*hi
            }
        }

        // Store: c0=(g,cc) c1=(g,cc+1) c2=(g+8,cc) c3=(g+8,cc+1)
        float* dstbuf = p ? g_xr : g_xl;
        const float* bb = p ? br : bl;
#pragma unroll
        for (int j = 0; j < 2; ++j) {
            int cc = nw + j * 8 + 2 * tig;
            float bias0 = bb[cc], bias1 = bb[cc + 1];
            int row0 = rowBase + mw + g;
            if (row0 < NNODE) {
                float2 o = make_float2(acc[j][0] + bias0, acc[j][1] + bias1);
                *(float2*)(dstbuf + row0 * 64 + cc) = o;
            }
            int row1 = row0 + 8;
            if (row1 < NNODE) {
                float2 o = make_float2(acc[j][2] + bias0, acc[j][3] + bias1);
                *(float2*)(dstbuf + row1 * 64 + cc) = o;
            }
        }
    }
}

// ---------------- degree histogram (4-wide batched atomics) -------------------
#define EDGE_GRID 782          // 782*256*4 >= NEDGE
__global__ void deg_kernel(const void* __restrict__ ei) {
    const int stride = EDGE_GRID * 256;
    const int i0 = blockIdx.x * 256 + threadIdx.x;
    const int is64 = g_is64;
    int d[4];
#pragma unroll
    for (int q = 0; q < 4; ++q) {
        int i = i0 + q * stride;
        d[q] = -1;
        if (i < NEDGE)
            d[q] = is64 ? (int)((const long long*)ei)[NEDGE + i]
                        : ((const int*)ei)[NEDGE + i];
    }
#pragma unroll
    for (int q = 0; q < 4; ++q)
        if (d[q] >= 0) atomicAdd(&g_deg[d[q]], 1);
}

// ---------------- per-block scan of degrees ----------------------------------
__global__ void scan_kernel() {
    int i = blockIdx.x * 1024 + threadIdx.x;
    int v = (i < NNODE) ? g_deg[i] : 0;
    int xx = v;
    int lane = threadIdx.x & 31, wid = threadIdx.x >> 5;
#pragma unroll
    for (int o = 1; o < 32; o <<= 1) {
        int y = __shfl_up_sync(0xffffffffu, xx, o);
        if (lane >= o) xx += y;
    }
    __shared__ int ws[32];
    if (lane == 31) ws[wid] = xx;
    __syncthreads();
    if (wid == 0) {
        int y = ws[lane];
#pragma unroll
        for (int o = 1; o < 32; o <<= 1) {
            int z = __shfl_up_sync(0xffffffffu, y, o);
            if (lane >= o) y += z;
        }
        ws[lane] = y;
    }
    __syncthreads();
    int incl = xx + (wid ? ws[wid - 1] : 0);
    if (i < NNODE) g_off[i] = incl - v;                  // block-local exclusive
    if (threadIdx.x == 1023) g_bsum[blockIdx.x] = incl;  // block total
}

// ---------------- fixup: parallel bsum load + add; also seeds cursor ----------
__global__ void fixup_kernel() {
    __shared__ int sb[NB_SCAN];
    __shared__ int pref;
    if (threadIdx.x < NB_SCAN) sb[threadIdx.x] = g_bsum[threadIdx.x];
    __syncthreads();
    if (threadIdx.x == 0) {
        int run = 0;
        for (int b = 0; b < blockIdx.x; ++b) run += sb[b];
        pref = run;
    }
    __syncthreads();
    int i = blockIdx.x * 1024 + threadIdx.x;
    if (i < NNODE) {
        int o = g_off[i] + pref;
        g_off[i]    = o;
        g_cursor[i] = o;          // scatter atomics start at the row offset
    }
}

// ---------------- scatter (4-wide batched: 4 atomics in flight) ---------------
__global__ void scatter_kernel(const void* __restrict__ ei) {
    const int stride = EDGE_GRID * 256;
    const int i0 = blockIdx.x * 256 + threadIdx.x;
    const int is64 = g_is64;
    int s[4], d[4], pos[4];
#pragma unroll
    for (int q = 0; q < 4; ++q) {
        int i = i0 + q * stride;
        d[q] = -1;
        if (i < NEDGE) {
            if (is64) {
                s[q] = (int)((const long long*)ei)[i];
                d[q] = (int)((const long long*)ei)[NEDGE + i];
            } else {
                s[q] = ((const int*)ei)[i];
                d[q] = ((const int*)ei)[NEDGE + i];
            }
        }
    }
#pragma unroll
    for (int q = 0; q < 4; ++q)
        if (d[q] >= 0) pos[q] = atomicAdd(&g_cursor[d[q]], 1);
#pragma unroll
    for (int q = 0; q < 4; ++q)
        if (d[q] >= 0) g_csr[pos[q]] = s[q];
}

// ---------------- aggregation: one warp per dst, online softmax (prefetch-1) --
__global__ void aggregate_kernel(const float* __restrict__ att,
                                 const float* __restrict__ bias,
                                 float* __restrict__ out) {
    int gw   = (blockIdx.x * blockDim.x + threadIdx.x) >> 5;
    int lane = threadIdx.x & 31;
    if (gw >= NNODE) return;
    const int dst = gw;

    const float2* xl2 = (const float2*)g_xl;
    const float2 a    = ((const float2*)att)[lane];
    const float2 xr   = ((const float2*)g_xr)[dst * 32 + lane];

    const int start = g_off[dst];
    const int cnt   = g_deg[dst];

    float m = -INFINITY, s = 0.f;
    float2 acc = make_float2(0.f, 0.f);

    // t = 0 is the self-loop; t in [1, cnt] are CSR edges.
    float2 v = xl2[dst * 32 + lane];

    for (int t = 0; t <= cnt; ++t) {
        float2 cv = v;
        if (t < cnt) {                      // prefetch next source row
            int sn = g_csr[start + t];
            v = xl2[sn * 32 + lane];
        }
        float h0 = cv.x + xr.x; h0 = h0 > 0.f ? h0 : NEG_SLOPE * h0;
        float h1 = cv.y + xr.y; h1 = h1 > 0.f ? h1 : NEG_SLOPE * h1;
        float p = a.x * h0 + a.y * h1;
#pragma unroll
        for (int o = 16; o; o >>= 1) p += __shfl_xor_sync(0xffffffffu, p, o);

        float mn = fmaxf(m, p);
        float cs = __expf(m - mn);   // 0 on the first iteration (m = -inf)
        float ce = __expf(p - mn);
        s     = s * cs + ce;
        acc.x = acc.x * cs + ce * cv.x;
        acc.y = acc.y * cs + ce * cv.y;
        m = mn;
    }

    float inv = 1.f / s;
    float2 bv = ((const float2*)bias)[lane];
    float2 o = make_float2(fmaxf(acc.x * inv + bv.x, 0.f),
                           fmaxf(acc.y * inv + bv.y, 0.f));
    ((float2*)out)[dst * 32 + lane] = o;
}

// ---------------- launch: GEMM starts immediately; CSR chain on side stream ---
extern "C" void kernel_launch(void* const* d_in, const int* in_sizes, int n_in,
                              void* d_out, int out_size) {
    const float* x    = (const float*)d_in[0];
    const float* Wl   = (const float*)d_in[1];
    const float* bl   = (const float*)d_in[2];
    const float* Wr   = (const float*)d_in[3];
    const float* br   = (const float*)d_in[4];
    const float* att  = (const float*)d_in[5];
    const float* bias = (const float*)d_in[6];
    const void*  ei   = (const void*)d_in[7];
    float* out = (float*)d_out;

    cudaStream_t s2;
    cudaEvent_t evFork, evJoin;
    cudaStreamCreateWithFlags(&s2, cudaStreamNonBlocking);
    cudaEventCreateWithFlags(&evFork, cudaEventDisableTiming);
    cudaEventCreateWithFlags(&evJoin, cudaEventDisableTiming);

    // Fork at capture start: side stream runs the whole CSR build.
    cudaEventRecord(evFork, 0);
    cudaStreamWaitEvent(s2, evFork, 0);
    init_kernel<<<NB_SCAN, 1024, 0, s2>>>(ei);
    deg_kernel<<<EDGE_GRID, 256, 0, s2>>>(ei);
    scan_kernel<<<NB_SCAN, 1024, 0, s2>>>();
    fixup_kernel<<<NB_SCAN, 1024, 0, s2>>>();
    scatter_kernel<<<EDGE_GRID, 256, 0, s2>>>(ei);
    cudaEventRecord(evJoin, s2);

    // Main stream: GEMM runs concurrently with the CSR build.
    gemm_kernel<<<(NNODE + 31) / 32, 256>>>(x, Wl, bl, Wr, br);

    cudaStreamWaitEvent(0, evJoin, 0);
    aggregate_kernel<<<(NNODE * 32 + 255) / 256, 256>>>(att, bias, out);

    cudaEventDestroy(evFork);
    cudaEventDestroy(evJoin);
    cudaStreamDestroy(s2);
}

// round 11
// speedup vs baseline: 1.3526x; 1.0087x over previous
#include <cuda_runtime.h>
#include <math.h>
#include <stdint.h>

#define NNODE 50000
#define NEDGE 800000
#define FIN   128
#define FOUT  64
#define NEG_SLOPE 0.2f
#define NB_SCAN 49            // ceil(NNODE/1024)

// ---------------- scratch (device globals: no allocation allowed) -------------
__device__ float g_xl[NNODE * FOUT];
__device__ float g_xr[NNODE * FOUT];
__device__ int   g_deg[NNODE];
__device__ int   g_off[NNODE];
__device__ int   g_cursor[NNODE];
__device__ int   g_csr[NEDGE];
__device__ int   g_bsum[NB_SCAN];
__device__ int   g_is64;

// ---------------- init: zero degree + detect edge_index dtype ----------------
__global__ void init_kernel(const void* __restrict__ ei) {
    int i = blockIdx.x * blockDim.x + threadIdx.x;
    for (int k = i; k < NNODE; k += gridDim.x * blockDim.x) g_deg[k] = 0;
    if (blockIdx.x == 0 && threadIdx.x < 32) {
        const long long* p = (const long long*)ei;
        int lane = threadIdx.x;
        int ok = 1;
#pragma unroll
        for (int j = 0; j < 8; ++j) {
            long long v = p[lane * 8 + j];
            if (v < 0 || v >= (long long)NNODE) ok = 0;
        }
        unsigned all = __ballot_sync(0xffffffffu, ok);
        if (lane == 0) g_is64 = (all == 0xffffffffu) ? 1 : 0;
    }
}

// ---------------- 3xBF16 tensor-core GEMM (48KB static smem) ------------------
// mma.m16n8k16.bf16, k=16 per MMA. v = hi + lo (both bf16);
// acc += hi*hi + hi*lo + lo*hi (fp32 accum). Residual ~2^-18 per product.

__device__ __forceinline__ void bf16_split(float e, float o,
                                           uint32_t& hi, uint32_t& lo) {
    asm("cvt.rn.bf16x2.f32 %0, %1, %2;" : "=r"(hi) : "f"(o), "f"(e));
    float eh = __uint_as_float(hi << 16);
    float oh = __uint_as_float(hi & 0xffff0000u);
    float er = e - eh;
    float orr = o - oh;
    asm("cvt.rn.bf16x2.f32 %0, %1, %2;" : "=r"(lo) : "f"(orr), "f"(er));
}

__device__ __forceinline__ void mma_bf16(float c[4], const uint32_t a[4],
                                         uint32_t b0, uint32_t b1) {
    asm volatile(
        "mma.sync.aligned.m16n8k16.row.col.f32.bf16.bf16.f32 "
        "{%0,%1,%2,%3}, {%4,%5,%6,%7}, {%8,%9}, {%0,%1,%2,%3};"
        : "+f"(c[0]), "+f"(c[1]), "+f"(c[2]), "+f"(c[3])
        : "r"(a[0]), "r"(a[1]), "r"(a[2]), "r"(a[3]), "r"(b0), "r"(b1));
}

__device__ __forceinline__ float2 lds2_sw(const float4* s4, int r, int c) {
    const float* p = (const float*)&s4[r * 32 + (((c >> 2)) ^ (r & 7))] + (c & 3);
    return *(const float2*)p;
}

__global__ void __launch_bounds__(256) gemm_kernel(
        const float* __restrict__ x,
        const float* __restrict__ Wl,
        const float* __restrict__ bl,
        const float* __restrict__ Wr,
        const float* __restrict__ br) {
    __shared__ float4 sX4[32 * 32];   // 16 KB
    __shared__ float4 sW4[64 * 32];   // 32 KB

    const int tid = threadIdx.x;
    const int rowBase = blockIdx.x * 32;

    const float4* x4 = (const float4*)x;
    for (int i = tid; i < 32 * 32; i += 256) {
        int r = i >> 5, c = i & 31;
        int row = rowBase + r;
        sX4[r * 32 + (c ^ (r & 7))] =
            (row < NNODE) ? x4[row * 32 + c] : make_float4(0.f, 0.f, 0.f, 0.f);
    }

    const int w    = tid >> 5;
    const int lane = tid & 31;
    const int g    = lane >> 2;
    const int tig  = lane & 3;
    const int mw   = (w >> 2) * 16;
    const int nw   = (w & 3) * 16;

#pragma unroll
    for (int p = 0; p < 2; ++p) {
        const float4* w4 = p ? (const float4*)Wr : (const float4*)Wl;
        __syncthreads();
        for (int i = tid; i < 64 * 32; i += 256) {
            int r = i >> 5, c = i & 31;
            sW4[r * 32 + (c ^ (r & 7))] = w4[r * 32 + c];
        }
        __syncthreads();

        float acc[2][4];
#pragma unroll
        for (int j = 0; j < 2; ++j)
#pragma unroll
            for (int q = 0; q < 4; ++q) acc[j][q] = 0.f;

        const int r0 = mw + g, r1 = mw + 8 + g;

#pragma unroll
        for (int ks = 0; ks < 8; ++ks) {
            const int k0 = ks * 16;
            float2 fa0 = lds2_sw(sX4, r0, k0 + 2 * tig);
            float2 fa1 = lds2_sw(sX4, r1, k0 + 2 * tig);
            float2 fa2 = lds2_sw(sX4, r0, k0 + 8 + 2 * tig);
            float2 fa3 = lds2_sw(sX4, r1, k0 + 8 + 2 * tig);
            uint32_t ahi[4], alo[4];
            bf16_split(fa0.x, fa0.y, ahi[0], alo[0]);
            bf16_split(fa1.x, fa1.y, ahi[1], alo[1]);
            bf16_split(fa2.x, fa2.y, ahi[2], alo[2]);
            bf16_split(fa3.x, fa3.y, ahi[3], alo[3]);

#pragma unroll
            for (int j = 0; j < 2; ++j) {
                const int br_ = nw + j * 8 + g;
                float2 fb0 = lds2_sw(sW4, br_, k0 + 2 * tig);
                float2 fb1 = lds2_sw(sW4, br_, k0 + 8 + 2 * tig);
                uint32_t b0h, b0l, b1h, b1l;
                bf16_split(fb0.x, fb0.y, b0h, b0l);
                bf16_split(fb1.x, fb1.y, b1h, b1l);
                mma_bf16(acc[j], ahi, b0h, b1h);   // hi*hi
                mma_bf16(acc[j], ahi, b0l, b1l);   // hi*lo
                mma_bf16(acc[j], alo, b0h, b1h);   // lo*hi
            }
        }

        float* dstbuf = p ? g_xr : g_xl;
        const float* bb = p ? br : bl;
#pragma unroll
        for (int j = 0; j < 2; ++j) {
            int cc = nw + j * 8 + 2 * tig;
            float bias0 = bb[cc], bias1 = bb[cc + 1];
            int row0 = rowBase + mw + g;
            if (row0 < NNODE) {
                float2 o = make_float2(acc[j][0] + bias0, acc[j][1] + bias1);
                *(float2*)(dstbuf + row0 * 64 + cc) = o;
            }
            int row1 = row0 + 8;
            if (row1 < NNODE) {
                float2 o = make_float2(acc[j][2] + bias0, acc[j][3] + bias1);
                *(float2*)(dstbuf + row1 * 64 + cc) = o;
            }
        }
    }
}

// ---------------- degree histogram (4-wide batched atomics) -------------------
#define EDGE_GRID 782          // 782*256*4 >= NEDGE
__global__ void deg_kernel(const void* __restrict__ ei) {
    const int stride = EDGE_GRID * 256;
    const int i0 = blockIdx.x * 256 + threadIdx.x;
    const int is64 = g_is64;
    int d[4];
#pragma unroll
    for (int q = 0; q < 4; ++q) {
        int i = i0 + q * stride;
        d[q] = -1;
        if (i < NEDGE)
            d[q] = is64 ? (int)((const long long*)ei)[NEDGE + i]
                        : ((const int*)ei)[NEDGE + i];
    }
#pragma unroll
    for (int q = 0; q < 4; ++q)
        if (d[q] >= 0) atomicAdd(&g_deg[d[q]], 1);
}

// ---------------- per-block scan of degrees ----------------------------------
__global__ void scan_kernel() {
    int i = blockIdx.x * 1024 + threadIdx.x;
    int v = (i < NNODE) ? g_deg[i] : 0;
    int xx = v;
    int lane = threadIdx.x & 31, wid = threadIdx.x >> 5;
#pragma unroll
    for (int o = 1; o < 32; o <<= 1) {
        int y = __shfl_up_sync(0xffffffffu, xx, o);
        if (lane >= o) xx += y;
    }
    __shared__ int ws[32];
    if (lane == 31) ws[wid] = xx;
    __syncthreads();
    if (wid == 0) {
        int y = ws[lane];
#pragma unroll
        for (int o = 1; o < 32; o <<= 1) {
            int z = __shfl_up_sync(0xffffffffu, y, o);
            if (lane >= o) y += z;
        }
        ws[lane] = y;
    }
    __syncthreads();
    int incl = xx + (wid ? ws[wid - 1] : 0);
    if (i < NNODE) g_off[i] = incl - v;                  // block-local exclusive
    if (threadIdx.x == 1023) g_bsum[blockIdx.x] = incl;  // block total
}

// ---------------- fixup: parallel bsum load + add; also seeds cursor ----------
__global__ void fixup_kernel() {
    __shared__ int sb[NB_SCAN];
    __shared__ int pref;
    if (threadIdx.x < NB_SCAN) sb[threadIdx.x] = g_bsum[threadIdx.x];
    __syncthreads();
    if (threadIdx.x == 0) {
        int run = 0;
        for (int b = 0; b < blockIdx.x; ++b) run += sb[b];
        pref = run;
    }
    __syncthreads();
    int i = blockIdx.x * 1024 + threadIdx.x;
    if (i < NNODE) {
        int o = g_off[i] + pref;
        g_off[i]    = o;
        g_cursor[i] = o;          // scatter atomics start at the row offset
    }
}

// ---------------- scatter (4-wide batched: 4 atomics in flight) ---------------
__global__ void scatter_kernel(const void* __restrict__ ei) {
    const int stride = EDGE_GRID * 256;
    const int i0 = blockIdx.x * 256 + threadIdx.x;
    const int is64 = g_is64;
    int s[4], d[4], pos[4];
#pragma unroll
    for (int q = 0; q < 4; ++q) {
        int i = i0 + q * stride;
        d[q] = -1;
        if (i < NEDGE) {
            if (is64) {
                s[q] = (int)((const long long*)ei)[i];
                d[q] = (int)((const long long*)ei)[NEDGE + i];
            } else {
                s[q] = ((const int*)ei)[i];
                d[q] = ((const int*)ei)[NEDGE + i];
            }
        }
    }
#pragma unroll
    for (int q = 0; q < 4; ++q)
        if (d[q] >= 0) pos[q] = atomicAdd(&g_cursor[d[q]], 1);
#pragma unroll
    for (int q = 0; q < 4; ++q)
        if (d[q] >= 0) g_csr[pos[q]] = s[q];
}

// ---------------- aggregation: warp/dst, single-exp online softmax ------------
__global__ void aggregate_kernel(const float* __restrict__ att,
                                 const float* __restrict__ bias,
                                 float* __restrict__ out) {
    int gw   = (blockIdx.x * blockDim.x + threadIdx.x) >> 5;
    int lane = threadIdx.x & 31;
    if (gw >= NNODE) return;
    const int dst = gw;

    const float2* xl2 = (const float2*)g_xl;
    const float2 a    = ((const float2*)att)[lane];
    const float2 xr   = ((const float2*)g_xr)[dst * 32 + lane];

    const int start = g_off[dst];
    const int cnt   = g_deg[dst];

    float m = -INFINITY, s = 0.f;
    float2 acc = make_float2(0.f, 0.f);

    // t = 0 is the self-loop; t in [1, cnt] are CSR edges.
    float2 v = xl2[dst * 32 + lane];

    for (int t = 0; t <= cnt; ++t) {
        float2 cv = v;
        if (t < cnt) {                      // prefetch next source row
            int sn = g_csr[start + t];
            v = xl2[sn * 32 + lane];
        }
        float h0 = cv.x + xr.x; h0 = h0 > 0.f ? h0 : NEG_SLOPE * h0;
        float h1 = cv.y + xr.y; h1 = h1 > 0.f ? h1 : NEG_SLOPE * h1;
        float p = a.x * h0 + a.y * h1;
#pragma unroll
        for (int o = 16; o; o >>= 1) p += __shfl_xor_sync(0xffffffffu, p, o);

        // one exp per item: e = exp(-|p - m|); on new max cs=e,ce=1 else cs=1,ce=e
        float d = p - m;                    // first iter: +inf
        bool newmax = d > 0.f;
        float e = __expf(newmax ? -d : d);  // exp(-inf) = 0 on first iter
        float cs = newmax ? e : 1.f;
        float ce = newmax ? 1.f : e;
        s     = s * cs + ce;
        acc.x = acc.x * cs + ce * cv.x;
        acc.y = acc.y * cs + ce * cv.y;
        if (newmax) m = p;
    }

    float inv = 1.f / s;
    float2 bv = ((const float2*)bias)[lane];
    float2 o = make_float2(fmaxf(acc.x * inv + bv.x, 0.f),
                           fmaxf(acc.y * inv + bv.y, 0.f));
    ((float2*)out)[dst * 32 + lane] = o;
}

// ---------------- launch: GEMM starts immediately; CSR chain on side stream ---
extern "C" void kernel_launch(void* const* d_in, const int* in_sizes, int n_in,
                              void* d_out, int out_size) {
    const float* x    = (const float*)d_in[0];
    const float* Wl   = (const float*)d_in[1];
    const float* bl   = (const float*)d_in[2];
    const float* Wr   = (const float*)d_in[3];
    const float* br   = (const float*)d_in[4];
    const float* att  = (const float*)d_in[5];
    const float* bias = (const float*)d_in[6];
    const void*  ei   = (const void*)d_in[7];
    float* out = (float*)d_out;

    cudaStream_t s2;
    cudaEvent_t evFork, evJoin;
    cudaStreamCreateWithFlags(&s2, cudaStreamNonBlocking);
    cudaEventCreateWithFlags(&evFork, cudaEventDisableTiming);
    cudaEventCreateWithFlags(&evJoin, cudaEventDisableTiming);

    cudaEventRecord(evFork, 0);
    cudaStreamWaitEvent(s2, evFork, 0);
    init_kernel<<<NB_SCAN, 1024, 0, s2>>>(ei);
    deg_kernel<<<EDGE_GRID, 256, 0, s2>>>(ei);
    scan_kernel<<<NB_SCAN, 1024, 0, s2>>>();
    fixup_kernel<<<NB_SCAN, 1024, 0, s2>>>();
    scatter_kernel<<<EDGE_GRID, 256, 0, s2>>>(ei);
    cudaEventRecord(evJoin, s2);

    gemm_kernel<<<(NNODE + 31) / 32, 256>>>(x, Wl, bl, Wr, br);

    cudaStreamWaitEvent(0, evJoin, 0);
    aggregate_kernel<<<(NNODE * 32 + 255) / 256, 256>>>(att, bias, out);

    cudaEventDestroy(evFork);
    cudaEventDestroy(evJoin);
    cudaStreamDestroy(s2);
}